// round 5
// baseline (speedup 1.0000x reference)
#include <cuda_runtime.h>
#include <math.h>

#define B_SAMP 8192
#define P_RAW  4849
#define P_PAD  4852

typedef unsigned long long ull;

__device__ float g_p[(size_t)B_SAMP * P_PAD];

// ---- packed fp32x2 helpers (sm_103a FFMA2 via PTX) ----
#define FFMA2(d, a, b, c) \
    asm("fma.rn.f32x2 %0, %1, %2, %3;" : "=l"(d) : "l"(a), "l"(b), "l"(c))

__device__ __forceinline__ ull pack2(float lo, float hi) {
    ull r; asm("mov.b64 %0, {%1, %2};" : "=l"(r) : "f"(lo), "f"(hi)); return r;
}
__device__ __forceinline__ void unpack2(ull v, float& lo, float& hi) {
    asm("mov.b64 {%0, %1}, %2;" : "=f"(lo), "=f"(hi) : "l"(v));
}
__device__ __forceinline__ float sqrt_apx(float v) {
    float r; asm("sqrt.approx.f32 %0, %1;" : "=f"(r) : "f"(v)); return r;
}

// ---------------------------------------------------------------------------
// Kernel 1: fused hypernet + GEMM. A stored PRE-DUPLICATED (a,a) in smem so
// the inner loop is pure LDS.128 + FFMA2 (no dup MOVs).
// ---------------------------------------------------------------------------
#define BM 64
#define BN 128
#define LDA 132
#define LDB 132
#define GEMM_THREADS 256
#define GEMM_SMEM ((96 * LDA + 96 * LDB) * 4)

__global__ __launch_bounds__(GEMM_THREADS)
void gemm_kernel(const float* __restrict__ x, const float* __restrict__ c,
                 const float* __restrict__ hw1, const float* __restrict__ hb1,
                 const float* __restrict__ hw2, const float* __restrict__ hb2)
{
    extern __shared__ float sm[];
    float* As = sm;                 // [96][LDA], dup'd pairs: 64 samples -> 128 floats
    float* Bs = sm + 96 * LDA;      // [96][LDB], 128 param cols

    const int t  = threadIdx.x;
    const int s0 = blockIdx.y * BM;
    const int p0 = blockIdx.x * BN;

    for (int i = t; i < BM * 96; i += GEMM_THREADS) {
        int sl = i / 96, k = i - sl * 96;
        int s = s0 + sl;
        float h = fmaf(x[s], hw1[2 * k], fmaf(c[s], hw1[2 * k + 1], hb1[k]));
        h = fmaxf(h, 0.f);
        *(float2*)(As + k * LDA + 2 * sl) = make_float2(h, h);
    }
    for (int i = t; i < BN * 96; i += GEMM_THREADS) {
        int pl = i / 96, k = i - pl * 96;
        int pp = p0 + pl;
        Bs[k * LDB + pl] = (pp < P_RAW) ? hw2[pp * 96 + k] : 0.f;
    }
    __syncthreads();

    const int tx = t & 15, ty = t >> 4;   // tx: 8-col group, ty: 4-row group
    ull acc[4][4];
#pragma unroll
    for (int i = 0; i < 4; i++)
#pragma unroll
        for (int j = 0; j < 4; j++) acc[i][j] = 0ull;

    const float* ap = As + 2 * (ty * 4);
    const float* bp = Bs + tx * 8;
#pragma unroll 4
    for (int k = 0; k < 96; k++) {
        ulonglong2 aq0 = *(const ulonglong2*)(ap + k * LDA);
        ulonglong2 aq1 = *(const ulonglong2*)(ap + k * LDA + 4);
        ulonglong2 bq0 = *(const ulonglong2*)(bp + k * LDB);
        ulonglong2 bq1 = *(const ulonglong2*)(bp + k * LDB + 4);
        ull ad[4] = {aq0.x, aq0.y, aq1.x, aq1.y};
        ull bq[4] = {bq0.x, bq0.y, bq1.x, bq1.y};
#pragma unroll
        for (int i = 0; i < 4; i++)
#pragma unroll
            for (int j = 0; j < 4; j++)
                FFMA2(acc[i][j], ad[i], bq[j], acc[i][j]);
    }

    float bias[8];
#pragma unroll
    for (int j = 0; j < 8; j++) {
        int pj = p0 + tx * 8 + j;
        bias[j] = (pj < P_RAW) ? hb2[pj] : 0.f;
    }
    bool full = (p0 + BN) <= P_RAW;
#pragma unroll
    for (int i = 0; i < 4; i++) {
        int s = s0 + ty * 4 + i;
        float* orow = g_p + (size_t)s * P_PAD + p0 + tx * 8;
        float a[8];
#pragma unroll
        for (int jp = 0; jp < 4; jp++) unpack2(acc[i][jp], a[2 * jp], a[2 * jp + 1]);
        if (full) {
            float4 v0 = {a[0] + bias[0], a[1] + bias[1], a[2] + bias[2], a[3] + bias[3]};
            float4 v1 = {a[4] + bias[4], a[5] + bias[5], a[6] + bias[6], a[7] + bias[7]};
            *(float4*)orow = v0;
            *(float4*)(orow + 4) = v1;
        } else {
#pragma unroll
            for (int j = 0; j < 8; j++) {
                int pj = p0 + tx * 8 + j;
                if (pj < P_RAW) orow[j] = a[j] + bias[j];
            }
        }
    }
}

// ---------------------------------------------------------------------------
// Kernel 2: per-sample Adam, balanced 1.5-row / k-packed layout.
//   lane l owns full row l (k-pair packed FFMA2);
//   rows 32..47 split by k-range across lane pairs (combine via 1 shfl).
// HD smem layout per k-pair j: [4j]=h_{2j} [4j+1]=h_{2j+1} [4j+2]=dh_{2j} [4j+3]=dh_{2j+1}
// ---------------------------------------------------------------------------
__device__ __forceinline__ float sigf(float z) {
    return __fdividef(1.f, 1.f + __expf(-z));
}

#define ADAM_WARPS 5

__global__ __launch_bounds__(32 * ADAM_WARPS, 2)
void adam_kernel(float* __restrict__ out)
{
    __shared__ __align__(16) float HD_all[ADAM_WARPS][96];
    const int lane = threadIdx.x & 31;
    const int wrp  = threadIdx.x >> 5;
    const int s    = blockIdx.x * ADAM_WARPS + wrp;
    if (s >= B_SAMP) return;
    float* HD = HD_all[wrp];

    const float* gp = g_p + (size_t)s * P_PAD;

    const int  rh    = 32 + (lane >> 1);      // split row handled by this lane pair
    const int  ko    = (lane & 1) * 24;       // k-offset of this lane's half
    const bool kzero = (lane & 1) == 0;
    const int  fpos  = 4 * (lane >> 1) + (lane & 1);        // HD slot of full row l
    const int  hpos  = 4 * (rh >> 1) + (rh & 1);            // HD slot of split row

    // Register-resident weights, k-pair packed straight from contiguous gmem.
    ull w1f[24], w2f[24], w1h[12], w2h[12];
    {
        const ulonglong2* p1 = (const ulonglong2*)(gp + 96 + lane * 48);
        const ulonglong2* p2 = (const ulonglong2*)(gp + 2448 + lane * 48);
#pragma unroll
        for (int q = 0; q < 12; q++) {
            ulonglong2 v1 = p1[q]; w1f[2 * q] = v1.x; w1f[2 * q + 1] = v1.y;
            ulonglong2 v2 = p2[q]; w2f[2 * q] = v2.x; w2f[2 * q + 1] = v2.y;
        }
        const ulonglong2* q1 = (const ulonglong2*)(gp + 96 + rh * 48 + ko);
        const ulonglong2* q2 = (const ulonglong2*)(gp + 2448 + rh * 48 + ko);
#pragma unroll
        for (int q = 0; q < 6; q++) {
            ulonglong2 v1 = q1[q]; w1h[2 * q] = v1.x; w1h[2 * q + 1] = v1.y;
            ulonglong2 v2 = q2[q]; w2h[2 * q] = v2.x; w2h[2 * q + 1] = v2.y;
        }
    }
    const float w0f = gp[lane],        b0f = gp[48 + lane];
    const float w0h = gp[rh],          b0h = gp[48 + rh];
    const float b1f = gp[2400 + lane], b1h = gp[2400 + rh];
    const float b2f = gp[4752 + lane], b2h = gp[4752 + rh];
    const float w3f = gp[4800 + lane], w3h = gp[4800 + rh];
    const int   hoff = ko >> 1;   // 0 or 12: k-pair offset for split-row loop

    float y = 0.f, m = 0.f, v = 0.f;
    float c1 = 1.f, c2 = 1.f;

#pragma unroll 1
    for (int step = 0; step < 20; step++) {
        // ----- layer 0 (scalar per owned row) -----
        {
            float z  = fmaf(w0f, y, b0f);
            float sg = sigf(z);
            HD[fpos]     = z * sg;
            HD[fpos + 2] = sg * fmaf(z, 1.f - sg, 1.f) * w0f;
            if (kzero) {
                float zh = fmaf(w0h, y, b0h);
                float sh = sigf(zh);
                HD[hpos]     = zh * sh;
                HD[hpos + 2] = sh * fmaf(zh, 1.f - sh, 1.f) * w0h;
            }
        }
        __syncwarp();

        // ----- layer 1: 4 independent FFMA2 chains -----
        ull az = pack2(b1f, 0.f), at = 0ull;
        ull hz = kzero ? pack2(b1h, 0.f) : 0ull, ht = 0ull;
#pragma unroll
        for (int q = 0; q < 24; q++) {
            ulonglong2 hd = *(const ulonglong2*)(HD + 4 * q);
            FFMA2(az, w1f[q], hd.x, az);
            FFMA2(at, w1f[q], hd.y, at);
        }
#pragma unroll
        for (int q = 0; q < 12; q++) {
            ulonglong2 hd = *(const ulonglong2*)(HD + 4 * (q + hoff));
            FFMA2(hz, w1h[q], hd.x, hz);
            FFMA2(ht, w1h[q], hd.y, ht);
        }
        __syncwarp();
        {
            float za, zo, ta, to2, pz, po, pt, pto;
            unpack2(az, za, zo); za += zo;
            unpack2(at, ta, to2); ta += to2;
            unpack2(hz, pz, po); pz += po;
            unpack2(ht, pt, pto); pt += pto;
            pz += __shfl_xor_sync(0xffffffffu, pz, 1);
            pt += __shfl_xor_sync(0xffffffffu, pt, 1);
            float sg = sigf(za);
            HD[fpos]     = za * sg;
            HD[fpos + 2] = sg * fmaf(za, 1.f - sg, 1.f) * ta;
            if (kzero) {
                float sh = sigf(pz);
                HD[hpos]     = pz * sh;
                HD[hpos + 2] = sh * fmaf(pz, 1.f - sh, 1.f) * pt;
            }
        }
        __syncwarp();

        // ----- layer 2 + output -----
        az = pack2(b2f, 0.f); at = 0ull;
        hz = kzero ? pack2(b2h, 0.f) : 0ull; ht = 0ull;
#pragma unroll
        for (int q = 0; q < 24; q++) {
            ulonglong2 hd = *(const ulonglong2*)(HD + 4 * q);
            FFMA2(az, w2f[q], hd.x, az);
            FFMA2(at, w2f[q], hd.y, at);
        }
#pragma unroll
        for (int q = 0; q < 12; q++) {
            ulonglong2 hd = *(const ulonglong2*)(HD + 4 * (q + hoff));
            FFMA2(hz, w2h[q], hd.x, hz);
            FFMA2(ht, w2h[q], hd.y, ht);
        }
        float g;
        {
            float za, zo, ta, to2, pz, po, pt, pto;
            unpack2(az, za, zo); za += zo;
            unpack2(at, ta, to2); ta += to2;
            unpack2(hz, pz, po); pz += po;
            unpack2(ht, pt, pto); pt += pto;
            pz += __shfl_xor_sync(0xffffffffu, pz, 1);
            pt += __shfl_xor_sync(0xffffffffu, pt, 1);
            float sg = sigf(za);
            g = w3f * (sg * fmaf(za, 1.f - sg, 1.f) * ta);
            if (kzero) {
                float sh = sigf(pz);
                g = fmaf(w3h, sh * fmaf(pz, 1.f - sh, 1.f) * pt, g);
            }
        }
#pragma unroll
        for (int o = 16; o; o >>= 1) g += __shfl_xor_sync(0xffffffffu, g, o);

        // ----- Adam update (fast approx div/sqrt; rel err ~1e-7) -----
        c1 *= 0.9f; c2 *= 0.999f;
        m = fmaf(0.9f, m, 0.1f * g);
        v = fmaf(0.999f, v, 0.001f * g * g);
        float mh = __fdividef(m, 1.f - c1);
        float vh = __fdividef(v, 1.f - c2);
        y -= 0.1f * __fdividef(mh, sqrt_apx(vh) + 1e-8f);
        __syncwarp();
    }

    if (lane == 0) out[s] = y;
}

// ---------------------------------------------------------------------------
extern "C" void kernel_launch(void* const* d_in, const int* in_sizes, int n_in,
                              void* d_out, int out_size)
{
    const float* x   = (const float*)d_in[0];
    const float* c   = (const float*)d_in[1];
    const float* hw1 = (const float*)d_in[2];
    const float* hb1 = (const float*)d_in[3];
    const float* hw2 = (const float*)d_in[4];
    const float* hb2 = (const float*)d_in[5];
    float* out = (float*)d_out;

    cudaFuncSetAttribute(gemm_kernel, cudaFuncAttributeMaxDynamicSharedMemorySize, GEMM_SMEM);

    dim3 ggrid((P_RAW + BN - 1) / BN, B_SAMP / BM);   // 38 x 128
    gemm_kernel<<<ggrid, GEMM_THREADS, GEMM_SMEM>>>(x, c, hw1, hb1, hw2, hb2);
    int ablocks = (B_SAMP + ADAM_WARPS - 1) / ADAM_WARPS;
    adam_kernel<<<ablocks, 32 * ADAM_WARPS>>>(out);
}

// round 8
// speedup vs baseline: 1.5001x; 1.5001x over previous
#include <cuda_runtime.h>
#include <math.h>

#define B_SAMP 8192
#define P_RAW  4849
#define P_PAD  4852

typedef unsigned long long ull;

__device__ float g_p[(size_t)B_SAMP * P_PAD];

// ---- packed fp32x2 helpers (sm_103a FFMA2 via PTX) ----
#define FFMA2(d, a, b, c) \
    asm("fma.rn.f32x2 %0, %1, %2, %3;" : "=l"(d) : "l"(a), "l"(b), "l"(c))

__device__ __forceinline__ ull pack2(float lo, float hi) {
    ull r; asm("mov.b64 %0, {%1, %2};" : "=l"(r) : "f"(lo), "f"(hi)); return r;
}
__device__ __forceinline__ ull dup2(float v) {
    ull r; asm("mov.b64 %0, {%1, %1};" : "=l"(r) : "f"(v)); return r;
}
__device__ __forceinline__ void unpack2(ull v, float& lo, float& hi) {
    asm("mov.b64 {%0, %1}, %2;" : "=f"(lo), "=f"(hi) : "l"(v));
}
__device__ __forceinline__ float sqrt_apx(float v) {
    float r; asm("sqrt.approx.f32 %0, %1;" : "=f"(r) : "f"(v)); return r;
}

// ---------------------------------------------------------------------------
// Kernel 1: fused hypernet + GEMM (R4 structure, conflict-free B mapping)
// Each thread: 8 samples x (cols tx*4..tx*4+3 and 64+tx*4..64+tx*4+3)
// ---------------------------------------------------------------------------
#define BM 128
#define BN 128
#define LDSS 132
#define GEMM_THREADS 256
#define GEMM_SMEM (2 * 96 * LDSS * 4)

__global__ __launch_bounds__(GEMM_THREADS)
void gemm_kernel(const float* __restrict__ x, const float* __restrict__ c,
                 const float* __restrict__ hw1, const float* __restrict__ hb1,
                 const float* __restrict__ hw2, const float* __restrict__ hb2)
{
    extern __shared__ float sm[];
    float* As = sm;
    float* Bs = sm + 96 * LDSS;

    const int t  = threadIdx.x;
    const int s0 = blockIdx.y * BM;
    const int p0 = blockIdx.x * BN;

    for (int i = t; i < BM * 96; i += GEMM_THREADS) {
        int sl = i / 96, k = i - sl * 96;
        int s = s0 + sl;
        float h = fmaf(x[s], hw1[2 * k], fmaf(c[s], hw1[2 * k + 1], hb1[k]));
        As[k * LDSS + sl] = fmaxf(h, 0.f);
    }
    for (int i = t; i < BN * 96; i += GEMM_THREADS) {
        int pl = i / 96, k = i - pl * 96;
        int pp = p0 + pl;
        Bs[k * LDSS + pl] = (pp < P_RAW) ? hw2[pp * 96 + k] : 0.f;
    }
    __syncthreads();

    const int tx = t & 15, ty = t >> 4;
    // acc[i][0..1]: cols tx*4+0..3 (pairs) ; acc[i][2..3]: cols 64+tx*4+0..3
    ull acc[8][4];
#pragma unroll
    for (int i = 0; i < 8; i++)
#pragma unroll
        for (int jp = 0; jp < 4; jp++) acc[i][jp] = 0ull;

    const float* ap  = As + ty * 8;
    const float* bpl = Bs + tx * 4;        // 16B lane stride: conflict-free
    const float* bph = Bs + 64 + tx * 4;
#pragma unroll 2
    for (int k = 0; k < 96; k++) {
        float4 a0 = *(const float4*)(ap + k * LDSS);
        float4 a1 = *(const float4*)(ap + k * LDSS + 4);
        ulonglong2 bq0 = *(const ulonglong2*)(bpl + k * LDSS);
        ulonglong2 bq1 = *(const ulonglong2*)(bph + k * LDSS);
        ull bq[4] = {bq0.x, bq0.y, bq1.x, bq1.y};
        ull ad[8] = {dup2(a0.x), dup2(a0.y), dup2(a0.z), dup2(a0.w),
                     dup2(a1.x), dup2(a1.y), dup2(a1.z), dup2(a1.w)};
#pragma unroll
        for (int i = 0; i < 8; i++)
#pragma unroll
            for (int jp = 0; jp < 4; jp++)
                FFMA2(acc[i][jp], ad[i], bq[jp], acc[i][jp]);
    }

    float bias[8];   // [0..3]: low group, [4..7]: high group
#pragma unroll
    for (int q = 0; q < 4; q++) {
        int jl = p0 + tx * 4 + q;
        int jh = p0 + 64 + tx * 4 + q;
        bias[q]     = (jl < P_RAW) ? hb2[jl] : 0.f;
        bias[4 + q] = (jh < P_RAW) ? hb2[jh] : 0.f;
    }
    bool full = (p0 + BN) <= P_RAW;
#pragma unroll
    for (int i = 0; i < 8; i++) {
        int s = s0 + ty * 8 + i;
        float* orow = g_p + (size_t)s * P_PAD + p0;
        float a[8];
#pragma unroll
        for (int jp = 0; jp < 4; jp++) unpack2(acc[i][jp], a[2 * jp], a[2 * jp + 1]);
        if (full) {
            float4 v0 = {a[0] + bias[0], a[1] + bias[1], a[2] + bias[2], a[3] + bias[3]};
            float4 v1 = {a[4] + bias[4], a[5] + bias[5], a[6] + bias[6], a[7] + bias[7]};
            *(float4*)(orow + tx * 4) = v0;
            *(float4*)(orow + 64 + tx * 4) = v1;
        } else {
#pragma unroll
            for (int q = 0; q < 4; q++) {
                int jl = p0 + tx * 4 + q;
                int jh = p0 + 64 + tx * 4 + q;
                if (jl < P_RAW) orow[tx * 4 + q]      = a[q] + bias[q];
                if (jh < P_RAW) orow[64 + tx * 4 + q] = a[4 + q] + bias[4 + q];
            }
        }
    }
}

// ---------------------------------------------------------------------------
// Kernel 2: per-sample Adam (R4 structure) + shfl reduction + fast tail.
// ---------------------------------------------------------------------------
__device__ __forceinline__ float sigf(float z) {
    return __fdividef(1.f, 1.f + __expf(-z));
}

__global__ __launch_bounds__(128, 2)
void adam_kernel(float* __restrict__ out)
{
    __shared__ __align__(16) float4 HD4_all[4][48];
    const int lane = threadIdx.x & 31;
    const int wrp  = threadIdx.x >> 5;
    const int s    = blockIdx.x * 4 + wrp;
    float4* HD4 = HD4_all[wrp];

    const float* gp = g_p + (size_t)s * P_PAD;

    const bool two = lane < 16;
    const int  ra  = lane;
    const int  rb  = two ? lane + 32 : lane;   // clamped; b-results unused when !two

    // Weight pairs: w1p[k] = (w1[ra][k], w1[rb][k]); same for w2p.  192 regs.
    ull w1p[48], w2p[48];
#pragma unroll
    for (int q = 0; q < 12; q++) {
        float4 A = ((const float4*)(gp + 96 + ra * 48))[q];
        float4 Bv = ((const float4*)(gp + 96 + rb * 48))[q];
        w1p[4 * q + 0] = pack2(A.x, Bv.x);
        w1p[4 * q + 1] = pack2(A.y, Bv.y);
        w1p[4 * q + 2] = pack2(A.z, Bv.z);
        w1p[4 * q + 3] = pack2(A.w, Bv.w);
    }
#pragma unroll
    for (int q = 0; q < 12; q++) {
        float4 A = ((const float4*)(gp + 2448 + ra * 48))[q];
        float4 Bv = ((const float4*)(gp + 2448 + rb * 48))[q];
        w2p[4 * q + 0] = pack2(A.x, Bv.x);
        w2p[4 * q + 1] = pack2(A.y, Bv.y);
        w2p[4 * q + 2] = pack2(A.z, Bv.z);
        w2p[4 * q + 3] = pack2(A.w, Bv.w);
    }
    const float w0a = gp[ra],        b0a = gp[48 + ra];
    const float w0b = gp[rb],        b0b = gp[48 + rb];
    const ull   b1pk = pack2(gp[2400 + ra], gp[2400 + rb]);
    const ull   b2pk = pack2(gp[4752 + ra], gp[4752 + rb]);
    const float w3a = gp[4800 + ra];
    const float w3b = two ? gp[4800 + rb] : 0.f;

    float y = 0.f, m = 0.f, v = 0.f;
    float c1 = 1.f, c2 = 1.f;

#pragma unroll 1
    for (int step = 0; step < 20; step++) {
        // ----- layer 0 -----
        {
            float z  = fmaf(w0a, y, b0a);
            float sg = sigf(z);
            float ha = z * sg;
            float da = sg * fmaf(z, 1.f - sg, 1.f) * w0a;
            HD4[ra] = make_float4(ha, ha, da, da);
            if (two) {
                float zb = fmaf(w0b, y, b0b);
                float sb = sigf(zb);
                float hb = zb * sb;
                float db = sb * fmaf(zb, 1.f - sb, 1.f) * w0b;
                HD4[lane + 32] = make_float4(hb, hb, db, db);
            }
        }
        __syncwarp();

        // ----- layer 1: packed value+tangent matvec -----
        ull accz = b1pk, acct = 0ull;
#pragma unroll
        for (int k = 0; k < 48; k++) {
            ulonglong2 q = *(const ulonglong2*)(HD4 + k);  // (h,h),(dh,dh)
            FFMA2(accz, w1p[k], q.x, accz);
            FFMA2(acct, w1p[k], q.y, acct);
        }
        __syncwarp();
        {
            float za, zb, ta, tb;
            unpack2(accz, za, zb);
            unpack2(acct, ta, tb);
            float sg = sigf(za);
            float ha = za * sg;
            float da = sg * fmaf(za, 1.f - sg, 1.f) * ta;
            HD4[ra] = make_float4(ha, ha, da, da);
            if (two) {
                float sb = sigf(zb);
                float hb = zb * sb;
                float db = sb * fmaf(zb, 1.f - sb, 1.f) * tb;
                HD4[lane + 32] = make_float4(hb, hb, db, db);
            }
        }
        __syncwarp();

        // ----- layer 2 + output -----
        accz = b2pk; acct = 0ull;
#pragma unroll
        for (int k = 0; k < 48; k++) {
            ulonglong2 q = *(const ulonglong2*)(HD4 + k);
            FFMA2(accz, w2p[k], q.x, accz);
            FFMA2(acct, w2p[k], q.y, acct);
        }
        float za, zb, ta, tb;
        unpack2(accz, za, zb);
        unpack2(acct, ta, tb);
        float sg = sigf(za);
        float g  = w3a * (sg * fmaf(za, 1.f - sg, 1.f) * ta);
        {
            float sb = sigf(zb);
            float gb = w3b * (sb * fmaf(zb, 1.f - sb, 1.f) * tb);
            if (two) g += gb;
        }
#pragma unroll
        for (int o = 16; o; o >>= 1) g += __shfl_xor_sync(0xffffffffu, g, o);

        // ----- Adam update (fast approx div/sqrt; validated rel_err ~6e-5) -----
        c1 *= 0.9f; c2 *= 0.999f;
        m = fmaf(0.9f, m, 0.1f * g);
        v = fmaf(0.999f, v, 0.001f * g * g);
        float mh = __fdividef(m, 1.f - c1);
        float vh = __fdividef(v, 1.f - c2);
        y -= 0.1f * __fdividef(mh, sqrt_apx(vh) + 1e-8f);
        __syncwarp();
    }

    if (lane == 0) out[s] = y;
}

// ---------------------------------------------------------------------------
extern "C" void kernel_launch(void* const* d_in, const int* in_sizes, int n_in,
                              void* d_out, int out_size)
{
    const float* x   = (const float*)d_in[0];
    const float* c   = (const float*)d_in[1];
    const float* hw1 = (const float*)d_in[2];
    const float* hb1 = (const float*)d_in[3];
    const float* hw2 = (const float*)d_in[4];
    const float* hb2 = (const float*)d_in[5];
    float* out = (float*)d_out;

    cudaFuncSetAttribute(gemm_kernel, cudaFuncAttributeMaxDynamicSharedMemorySize, GEMM_SMEM);

    dim3 ggrid((P_RAW + BN - 1) / BN, B_SAMP / BM);   // 38 x 64
    gemm_kernel<<<ggrid, GEMM_THREADS, GEMM_SMEM>>>(x, c, hw1, hb1, hw2, hb2);
    adam_kernel<<<B_SAMP / 4, 128>>>(out);
}

// round 10
// speedup vs baseline: 1.5076x; 1.0050x over previous
#include <cuda_runtime.h>
#include <math.h>

#define B_SAMP 8192
#define P_RAW  4849
#define P_PAD  4852

typedef unsigned long long ull;

__device__ float g_p[(size_t)B_SAMP * P_PAD];

// ---- packed fp32x2 helpers (sm_103a FFMA2 via PTX) ----
#define FFMA2(d, a, b, c) \
    asm("fma.rn.f32x2 %0, %1, %2, %3;" : "=l"(d) : "l"(a), "l"(b), "l"(c))
#define ADD2(d, a, b) \
    asm("add.rn.f32x2 %0, %1, %2;" : "=l"(d) : "l"(a), "l"(b))

__device__ __forceinline__ ull pack2(float lo, float hi) {
    ull r; asm("mov.b64 %0, {%1, %2};" : "=l"(r) : "f"(lo), "f"(hi)); return r;
}
__device__ __forceinline__ ull dup2(float v) {
    ull r; asm("mov.b64 %0, {%1, %1};" : "=l"(r) : "f"(v)); return r;
}
__device__ __forceinline__ void unpack2(ull v, float& lo, float& hi) {
    asm("mov.b64 {%0, %1}, %2;" : "=f"(lo), "=f"(hi) : "l"(v));
}
__device__ __forceinline__ float sqrt_apx(float v) {
    float r; asm("sqrt.approx.f32 %0, %1;" : "=f"(r) : "f"(v)); return r;
}

// ---------------------------------------------------------------------------
// Kernel 1: fused hypernet + GEMM (R8 structure, conflict-free B mapping)
// ---------------------------------------------------------------------------
#define BM 128
#define BN 128
#define LDSS 132
#define GEMM_THREADS 256
#define GEMM_SMEM (2 * 96 * LDSS * 4)

__global__ __launch_bounds__(GEMM_THREADS)
void gemm_kernel(const float* __restrict__ x, const float* __restrict__ c,
                 const float* __restrict__ hw1, const float* __restrict__ hb1,
                 const float* __restrict__ hw2, const float* __restrict__ hb2)
{
    extern __shared__ float sm[];
    float* As = sm;
    float* Bs = sm + 96 * LDSS;

    const int t  = threadIdx.x;
    const int s0 = blockIdx.y * BM;
    const int p0 = blockIdx.x * BN;

    for (int i = t; i < BM * 96; i += GEMM_THREADS) {
        int sl = i / 96, k = i - sl * 96;
        int s = s0 + sl;
        float h = fmaf(x[s], hw1[2 * k], fmaf(c[s], hw1[2 * k + 1], hb1[k]));
        As[k * LDSS + sl] = fmaxf(h, 0.f);
    }
    for (int i = t; i < BN * 96; i += GEMM_THREADS) {
        int pl = i / 96, k = i - pl * 96;
        int pp = p0 + pl;
        Bs[k * LDSS + pl] = (pp < P_RAW) ? hw2[pp * 96 + k] : 0.f;
    }
    __syncthreads();

    const int tx = t & 15, ty = t >> 4;
    ull acc[8][4];
#pragma unroll
    for (int i = 0; i < 8; i++)
#pragma unroll
        for (int jp = 0; jp < 4; jp++) acc[i][jp] = 0ull;

    const float* ap  = As + ty * 8;
    const float* bpl = Bs + tx * 4;        // 16B lane stride: conflict-free
    const float* bph = Bs + 64 + tx * 4;
#pragma unroll 2
    for (int k = 0; k < 96; k++) {
        float4 a0 = *(const float4*)(ap + k * LDSS);
        float4 a1 = *(const float4*)(ap + k * LDSS + 4);
        ulonglong2 bq0 = *(const ulonglong2*)(bpl + k * LDSS);
        ulonglong2 bq1 = *(const ulonglong2*)(bph + k * LDSS);
        ull bq[4] = {bq0.x, bq0.y, bq1.x, bq1.y};
        ull ad[8] = {dup2(a0.x), dup2(a0.y), dup2(a0.z), dup2(a0.w),
                     dup2(a1.x), dup2(a1.y), dup2(a1.z), dup2(a1.w)};
#pragma unroll
        for (int i = 0; i < 8; i++)
#pragma unroll
            for (int jp = 0; jp < 4; jp++)
                FFMA2(acc[i][jp], ad[i], bq[jp], acc[i][jp]);
    }

    float bias[8];
#pragma unroll
    for (int q = 0; q < 4; q++) {
        int jl = p0 + tx * 4 + q;
        int jh = p0 + 64 + tx * 4 + q;
        bias[q]     = (jl < P_RAW) ? hb2[jl] : 0.f;
        bias[4 + q] = (jh < P_RAW) ? hb2[jh] : 0.f;
    }
    bool full = (p0 + BN) <= P_RAW;
#pragma unroll
    for (int i = 0; i < 8; i++) {
        int s = s0 + ty * 8 + i;
        float* orow = g_p + (size_t)s * P_PAD + p0;
        float a[8];
#pragma unroll
        for (int jp = 0; jp < 4; jp++) unpack2(acc[i][jp], a[2 * jp], a[2 * jp + 1]);
        if (full) {
            float4 v0 = {a[0] + bias[0], a[1] + bias[1], a[2] + bias[2], a[3] + bias[3]};
            float4 v1 = {a[4] + bias[4], a[5] + bias[5], a[6] + bias[6], a[7] + bias[7]};
            *(float4*)(orow + tx * 4) = v0;
            *(float4*)(orow + 64 + tx * 4) = v1;
        } else {
#pragma unroll
            for (int q = 0; q < 4; q++) {
                int jl = p0 + tx * 4 + q;
                int jh = p0 + 64 + tx * 4 + q;
                if (jl < P_RAW) orow[tx * 4 + q]      = a[q] + bias[q];
                if (jh < P_RAW) orow[64 + tx * 4 + q] = a[4 + q] + bias[4 + q];
            }
        }
    }
}

// ---------------------------------------------------------------------------
// Kernel 2: per-sample Adam (R8 structure) + SPLIT ACCUMULATOR CHAINS:
// 4 independent FFMA2 chains of depth 24 instead of 2 chains of depth 48.
// ---------------------------------------------------------------------------
__device__ __forceinline__ float sigf(float z) {
    return __fdividef(1.f, 1.f + __expf(-z));
}

__global__ __launch_bounds__(128, 2)
void adam_kernel(float* __restrict__ out)
{
    __shared__ __align__(16) float4 HD4_all[4][48];
    const int lane = threadIdx.x & 31;
    const int wrp  = threadIdx.x >> 5;
    const int s    = blockIdx.x * 4 + wrp;
    float4* HD4 = HD4_all[wrp];

    const float* gp = g_p + (size_t)s * P_PAD;

    const bool two = lane < 16;
    const int  ra  = lane;
    const int  rb  = two ? lane + 32 : lane;   // clamped; b-results unused when !two

    // Weight pairs: w1p[k] = (w1[ra][k], w1[rb][k]); same for w2p.  192 regs.
    ull w1p[48], w2p[48];
#pragma unroll
    for (int q = 0; q < 12; q++) {
        float4 A = ((const float4*)(gp + 96 + ra * 48))[q];
        float4 Bv = ((const float4*)(gp + 96 + rb * 48))[q];
        w1p[4 * q + 0] = pack2(A.x, Bv.x);
        w1p[4 * q + 1] = pack2(A.y, Bv.y);
        w1p[4 * q + 2] = pack2(A.z, Bv.z);
        w1p[4 * q + 3] = pack2(A.w, Bv.w);
    }
#pragma unroll
    for (int q = 0; q < 12; q++) {
        float4 A = ((const float4*)(gp + 2448 + ra * 48))[q];
        float4 Bv = ((const float4*)(gp + 2448 + rb * 48))[q];
        w2p[4 * q + 0] = pack2(A.x, Bv.x);
        w2p[4 * q + 1] = pack2(A.y, Bv.y);
        w2p[4 * q + 2] = pack2(A.z, Bv.z);
        w2p[4 * q + 3] = pack2(A.w, Bv.w);
    }
    const float w0a = gp[ra],        b0a = gp[48 + ra];
    const float w0b = gp[rb],        b0b = gp[48 + rb];
    const ull   b1pk = pack2(gp[2400 + ra], gp[2400 + rb]);
    const ull   b2pk = pack2(gp[4752 + ra], gp[4752 + rb]);
    const float w3a = gp[4800 + ra];
    const float w3b = two ? gp[4800 + rb] : 0.f;

    float y = 0.f, m = 0.f, v = 0.f;
    float c1 = 1.f, c2 = 1.f;

#pragma unroll 1
    for (int step = 0; step < 20; step++) {
        // ----- layer 0 -----
        {
            float z  = fmaf(w0a, y, b0a);
            float sg = sigf(z);
            float ha = z * sg;
            float da = sg * fmaf(z, 1.f - sg, 1.f) * w0a;
            HD4[ra] = make_float4(ha, ha, da, da);
            if (two) {
                float zb = fmaf(w0b, y, b0b);
                float sb = sigf(zb);
                float hb = zb * sb;
                float db = sb * fmaf(zb, 1.f - sb, 1.f) * w0b;
                HD4[lane + 32] = make_float4(hb, hb, db, db);
            }
        }
        __syncwarp();

        // ----- layer 1: 4 split chains (depth 24 each) -----
        ull az0 = b1pk, az1 = 0ull, at0 = 0ull, at1 = 0ull;
#pragma unroll
        for (int k = 0; k < 48; k += 2) {
            ulonglong2 q0 = *(const ulonglong2*)(HD4 + k);
            ulonglong2 q1 = *(const ulonglong2*)(HD4 + k + 1);
            FFMA2(az0, w1p[k],     q0.x, az0);
            FFMA2(at0, w1p[k],     q0.y, at0);
            FFMA2(az1, w1p[k + 1], q1.x, az1);
            FFMA2(at1, w1p[k + 1], q1.y, at1);
        }
        __syncwarp();
        {
            ull accz, acct;
            ADD2(accz, az0, az1);
            ADD2(acct, at0, at1);
            float za, zb, ta, tb;
            unpack2(accz, za, zb);
            unpack2(acct, ta, tb);
            float sg = sigf(za);
            float ha = za * sg;
            float da = sg * fmaf(za, 1.f - sg, 1.f) * ta;
            HD4[ra] = make_float4(ha, ha, da, da);
            if (two) {
                float sb = sigf(zb);
                float hb = zb * sb;
                float db = sb * fmaf(zb, 1.f - sb, 1.f) * tb;
                HD4[lane + 32] = make_float4(hb, hb, db, db);
            }
        }
        __syncwarp();

        // ----- layer 2 + output: 4 split chains -----
        az0 = b2pk; az1 = 0ull; at0 = 0ull; at1 = 0ull;
#pragma unroll
        for (int k = 0; k < 48; k += 2) {
            ulonglong2 q0 = *(const ulonglong2*)(HD4 + k);
            ulonglong2 q1 = *(const ulonglong2*)(HD4 + k + 1);
            FFMA2(az0, w2p[k],     q0.x, az0);
            FFMA2(at0, w2p[k],     q0.y, at0);
            FFMA2(az1, w2p[k + 1], q1.x, az1);
            FFMA2(at1, w2p[k + 1], q1.y, at1);
        }
        float za, zb, ta, tb;
        {
            ull accz, acct;
            ADD2(accz, az0, az1);
            ADD2(acct, at0, at1);
            unpack2(accz, za, zb);
            unpack2(acct, ta, tb);
        }
        float sg = sigf(za);
        float g  = w3a * (sg * fmaf(za, 1.f - sg, 1.f) * ta);
        {
            float sb = sigf(zb);
            float gb = w3b * (sb * fmaf(zb, 1.f - sb, 1.f) * tb);
            if (two) g += gb;
        }
#pragma unroll
        for (int o = 16; o; o >>= 1) g += __shfl_xor_sync(0xffffffffu, g, o);

        // ----- Adam update (fast approx div/sqrt; validated rel_err ~5e-5) -----
        c1 *= 0.9f; c2 *= 0.999f;
        m = fmaf(0.9f, m, 0.1f * g);
        v = fmaf(0.999f, v, 0.001f * g * g);
        float mh = __fdividef(m, 1.f - c1);
        float vh = __fdividef(v, 1.f - c2);
        y -= 0.1f * __fdividef(mh, sqrt_apx(vh) + 1e-8f);
        __syncwarp();
    }

    if (lane == 0) out[s] = y;
}

// ---------------------------------------------------------------------------
extern "C" void kernel_launch(void* const* d_in, const int* in_sizes, int n_in,
                              void* d_out, int out_size)
{
    const float* x   = (const float*)d_in[0];
    const float* c   = (const float*)d_in[1];
    const float* hw1 = (const float*)d_in[2];
    const float* hb1 = (const float*)d_in[3];
    const float* hw2 = (const float*)d_in[4];
    const float* hb2 = (const float*)d_in[5];
    float* out = (float*)d_out;

    cudaFuncSetAttribute(gemm_kernel, cudaFuncAttributeMaxDynamicSharedMemorySize, GEMM_SMEM);

    dim3 ggrid((P_RAW + BN - 1) / BN, B_SAMP / BM);   // 38 x 64
    gemm_kernel<<<ggrid, GEMM_THREADS, GEMM_SMEM>>>(x, c, hw1, hb1, hw2, hb2);
    adam_kernel<<<B_SAMP / 4, 128>>>(out);
}

// round 13
// speedup vs baseline: 1.8198x; 1.2071x over previous
#include <cuda_runtime.h>
#include <math.h>

#define B_SAMP 8192
#define P_RAW  4849
#define P_PAD  4852

typedef unsigned long long ull;

__device__ float g_p[(size_t)B_SAMP * P_PAD];

// ---- packed fp32x2 helpers (sm_103a FFMA2 via PTX) ----
#define FFMA2(d, a, b, c) \
    asm("fma.rn.f32x2 %0, %1, %2, %3;" : "=l"(d) : "l"(a), "l"(b), "l"(c))

__device__ __forceinline__ ull pack2(float lo, float hi) {
    ull r; asm("mov.b64 %0, {%1, %2};" : "=l"(r) : "f"(lo), "f"(hi)); return r;
}
__device__ __forceinline__ ull dup2(float v) {
    ull r; asm("mov.b64 %0, {%1, %1};" : "=l"(r) : "f"(v)); return r;
}
__device__ __forceinline__ void unpack2(ull v, float& lo, float& hi) {
    asm("mov.b64 {%0, %1}, %2;" : "=f"(lo), "=f"(hi) : "l"(v));
}
__device__ __forceinline__ float sqrt_apx(float v) {
    float r; asm("sqrt.approx.f32 %0, %1;" : "=f"(r) : "f"(v)); return r;
}

// ---------------------------------------------------------------------------
// Kernel 1: fused hypernet + GEMM (unchanged R8 structure)
// ---------------------------------------------------------------------------
#define BM 128
#define BN 128
#define LDSS 132
#define GEMM_THREADS 256
#define GEMM_SMEM (2 * 96 * LDSS * 4)

__global__ __launch_bounds__(GEMM_THREADS)
void gemm_kernel(const float* __restrict__ x, const float* __restrict__ c,
                 const float* __restrict__ hw1, const float* __restrict__ hb1,
                 const float* __restrict__ hw2, const float* __restrict__ hb2)
{
    extern __shared__ float sm[];
    float* As = sm;
    float* Bs = sm + 96 * LDSS;

    const int t  = threadIdx.x;
    const int s0 = blockIdx.y * BM;
    const int p0 = blockIdx.x * BN;

    for (int i = t; i < BM * 96; i += GEMM_THREADS) {
        int sl = i / 96, k = i - sl * 96;
        int s = s0 + sl;
        float h = fmaf(x[s], hw1[2 * k], fmaf(c[s], hw1[2 * k + 1], hb1[k]));
        As[k * LDSS + sl] = fmaxf(h, 0.f);
    }
    for (int i = t; i < BN * 96; i += GEMM_THREADS) {
        int pl = i / 96, k = i - pl * 96;
        int pp = p0 + pl;
        Bs[k * LDSS + pl] = (pp < P_RAW) ? hw2[pp * 96 + k] : 0.f;
    }
    __syncthreads();

    const int tx = t & 15, ty = t >> 4;
    ull acc[8][4];
#pragma unroll
    for (int i = 0; i < 8; i++)
#pragma unroll
        for (int jp = 0; jp < 4; jp++) acc[i][jp] = 0ull;

    const float* ap  = As + ty * 8;
    const float* bpl = Bs + tx * 4;
    const float* bph = Bs + 64 + tx * 4;
#pragma unroll 2
    for (int k = 0; k < 96; k++) {
        float4 a0 = *(const float4*)(ap + k * LDSS);
        float4 a1 = *(const float4*)(ap + k * LDSS + 4);
        ulonglong2 bq0 = *(const ulonglong2*)(bpl + k * LDSS);
        ulonglong2 bq1 = *(const ulonglong2*)(bph + k * LDSS);
        ull bq[4] = {bq0.x, bq0.y, bq1.x, bq1.y};
        ull ad[8] = {dup2(a0.x), dup2(a0.y), dup2(a0.z), dup2(a0.w),
                     dup2(a1.x), dup2(a1.y), dup2(a1.z), dup2(a1.w)};
#pragma unroll
        for (int i = 0; i < 8; i++)
#pragma unroll
            for (int jp = 0; jp < 4; jp++)
                FFMA2(acc[i][jp], ad[i], bq[jp], acc[i][jp]);
    }

    float bias[8];
#pragma unroll
    for (int q = 0; q < 4; q++) {
        int jl = p0 + tx * 4 + q;
        int jh = p0 + 64 + tx * 4 + q;
        bias[q]     = (jl < P_RAW) ? hb2[jl] : 0.f;
        bias[4 + q] = (jh < P_RAW) ? hb2[jh] : 0.f;
    }
    bool full = (p0 + BN) <= P_RAW;
#pragma unroll
    for (int i = 0; i < 8; i++) {
        int s = s0 + ty * 8 + i;
        float* orow = g_p + (size_t)s * P_PAD + p0;
        float a[8];
#pragma unroll
        for (int jp = 0; jp < 4; jp++) unpack2(acc[i][jp], a[2 * jp], a[2 * jp + 1]);
        if (full) {
            float4 v0 = {a[0] + bias[0], a[1] + bias[1], a[2] + bias[2], a[3] + bias[3]};
            float4 v1 = {a[4] + bias[4], a[5] + bias[5], a[6] + bias[6], a[7] + bias[7]};
            *(float4*)(orow + tx * 4) = v0;
            *(float4*)(orow + 64 + tx * 4) = v1;
        } else {
#pragma unroll
            for (int q = 0; q < 4; q++) {
                int jl = p0 + tx * 4 + q;
                int jh = p0 + 64 + tx * 4 + q;
                if (jl < P_RAW) orow[tx * 4 + q]      = a[q] + bias[q];
                if (jh < P_RAW) orow[64 + tx * 4 + q] = a[4 + q] + bias[4 + q];
            }
        }
    }
}

// ---------------------------------------------------------------------------
// Kernel 2: Adam, split-k row-triple layout.
//   lane = (p = lane&15, half = lane>>4). Lane owns rows 3p..3p+2 over
//   k in [24*half, 24*half+24). Matvec: 12 LDS.128 + 72 FFMA2 per lane.
//   Halves combined via one shfl_xor(16) of packed (z,t) per row.
// HD quad j: (h_{2j}, h_{2j+1}, dh_{2j}, dh_{2j+1}),  j = 0..23.
// ---------------------------------------------------------------------------
__device__ __forceinline__ float sigf(float z) {
    return __fdividef(1.f, 1.f + __expf(-z));
}

__global__ __launch_bounds__(128, 2)
void adam_kernel(float* __restrict__ out)
{
    __shared__ __align__(16) float4 HD4_all[4][24];
    const int lane = threadIdx.x & 31;
    const int wrp  = threadIdx.x >> 5;
    const int s    = blockIdx.x * 4 + wrp;
    float4* HD4 = HD4_all[wrp];
    float*  HDf = (float*)HD4;

    const float* gp = g_p + (size_t)s * P_PAD;

    const int p    = lane & 15;
    const int half = lane >> 4;          // 0: k 0..23, 1: k 24..47
    const int ko   = half * 24;
    const int r0   = 3 * p;              // rows r0, r0+1, r0+2

    // Register-resident weight halves, k-pair packed.  w[r][j] covers
    // k = ko+2j, ko+2j+1 of row r0+r.   3 rows x 12 pairs x 2 mats = 144 regs.
    ull w1p[3][12], w2p[3][12];
#pragma unroll
    for (int r = 0; r < 3; r++) {
        const float4* p1 = (const float4*)(gp + 96   + (r0 + r) * 48 + ko);
        const float4* p2 = (const float4*)(gp + 2448 + (r0 + r) * 48 + ko);
#pragma unroll
        for (int q = 0; q < 6; q++) {
            float4 v1 = p1[q];
            w1p[r][2 * q]     = pack2(v1.x, v1.y);
            w1p[r][2 * q + 1] = pack2(v1.z, v1.w);
            float4 v2 = p2[q];
            w2p[r][2 * q]     = pack2(v2.x, v2.y);
            w2p[r][2 * q + 1] = pack2(v2.z, v2.w);
        }
    }
    float w0r[3], b0r[3], b1r[3], b2r[3], w3r[3];
#pragma unroll
    for (int r = 0; r < 3; r++) {
        w0r[r] = gp[r0 + r];
        b0r[r] = gp[48 + r0 + r];
        b1r[r] = gp[2400 + r0 + r];
        b2r[r] = gp[4752 + r0 + r];
        w3r[r] = gp[4800 + r0 + r];
    }
    // HD slot indices for this lane's 3 rows (h slot; dh slot = +2 within quad)
    int hslot[3];
#pragma unroll
    for (int r = 0; r < 3; r++) {
        int rr = r0 + r;
        hslot[r] = 4 * (rr >> 1) + (rr & 1);
    }

    float y = 0.f, m = 0.f, v = 0.f;
    float c1 = 1.f, c2 = 1.f;

#pragma unroll 1
    for (int step = 0; step < 20; step++) {
        // ----- layer 0: lanes<16 store h, lanes>=16 store dh -----
#pragma unroll
        for (int r = 0; r < 3; r++) {
            float z  = fmaf(w0r[r], y, b0r[r]);
            float sg = sigf(z);
            if (half == 0) HDf[hslot[r]]     = z * sg;
            else           HDf[hslot[r] + 2] = sg * fmaf(z, 1.f - sg, 1.f) * w0r[r];
        }
        __syncwarp();

        // ----- layer 1 matvec (k-half per lane) -----
        ull az[3] = {0ull, 0ull, 0ull}, at[3] = {0ull, 0ull, 0ull};
#pragma unroll
        for (int j = 0; j < 12; j++) {
            ulonglong2 q = *(const ulonglong2*)(HD4 + half * 12 + j);
#pragma unroll
            for (int r = 0; r < 3; r++) {
                FFMA2(az[r], w1p[r][j], q.x, az[r]);
                FFMA2(at[r], w1p[r][j], q.y, at[r]);
            }
        }
        // combine halves: zt packed per row, shfl-xor 16
        float zf[3], tf[3];
#pragma unroll
        for (int r = 0; r < 3; r++) {
            float zl, zh2, tl, th2;
            unpack2(az[r], zl, zh2);
            unpack2(at[r], tl, th2);
            ull zt = pack2(zl + zh2, tl + th2);
            zt += 0;  // keep as ull
            ull ot = __shfl_xor_sync(0xffffffffu, zt, 16);
            float zo, to2;
            unpack2(zt, zl, tl);
            unpack2(ot, zo, to2);
            zf[r] = zl + zo + b1r[r];
            tf[r] = tl + to2;
        }
        __syncwarp();   // all reads of HD done before overwrite
#pragma unroll
        for (int r = 0; r < 3; r++) {
            float sg = sigf(zf[r]);
            if (half == 0) HDf[hslot[r]]     = zf[r] * sg;
            else           HDf[hslot[r] + 2] = sg * fmaf(zf[r], 1.f - sg, 1.f) * tf[r];
        }
        __syncwarp();

        // ----- layer 2 matvec -----
#pragma unroll
        for (int r = 0; r < 3; r++) { az[r] = 0ull; at[r] = 0ull; }
#pragma unroll
        for (int j = 0; j < 12; j++) {
            ulonglong2 q = *(const ulonglong2*)(HD4 + half * 12 + j);
#pragma unroll
            for (int r = 0; r < 3; r++) {
                FFMA2(az[r], w2p[r][j], q.x, az[r]);
                FFMA2(at[r], w2p[r][j], q.y, at[r]);
            }
        }
        float g = 0.f;
#pragma unroll
        for (int r = 0; r < 3; r++) {
            float zl, zh2, tl, th2;
            unpack2(az[r], zl, zh2);
            unpack2(at[r], tl, th2);
            ull zt = pack2(zl + zh2, tl + th2);
            ull ot = __shfl_xor_sync(0xffffffffu, zt, 16);
            float zo, to2;
            unpack2(zt, zl, tl);
            unpack2(ot, zo, to2);
            float zz = zl + zo + b2r[r];
            float tt = tl + to2;
            float sg = sigf(zz);
            g = fmaf(w3r[r], sg * fmaf(zz, 1.f - sg, 1.f) * tt, g);
        }
        if (half) g = 0.f;          // rows duplicated across halves; count once
#pragma unroll
        for (int o = 16; o; o >>= 1) g += __shfl_xor_sync(0xffffffffu, g, o);

        // ----- Adam update (fast approx div/sqrt) -----
        c1 *= 0.9f; c2 *= 0.999f;
        m = fmaf(0.9f, m, 0.1f * g);
        v = fmaf(0.999f, v, 0.001f * g * g);
        float mh = __fdividef(m, 1.f - c1);
        float vh = __fdividef(v, 1.f - c2);
        y -= 0.1f * __fdividef(mh, sqrt_apx(vh) + 1e-8f);
        __syncwarp();
    }

    if (lane == 0) out[s] = y;
}

// ---------------------------------------------------------------------------
extern "C" void kernel_launch(void* const* d_in, const int* in_sizes, int n_in,
                              void* d_out, int out_size)
{
    const float* x   = (const float*)d_in[0];
    const float* c   = (const float*)d_in[1];
    const float* hw1 = (const float*)d_in[2];
    const float* hb1 = (const float*)d_in[3];
    const float* hw2 = (const float*)d_in[4];
    const float* hb2 = (const float*)d_in[5];
    float* out = (float*)d_out;

    cudaFuncSetAttribute(gemm_kernel, cudaFuncAttributeMaxDynamicSharedMemorySize, GEMM_SMEM);

    dim3 ggrid((P_RAW + BN - 1) / BN, B_SAMP / BM);   // 38 x 64
    gemm_kernel<<<ggrid, GEMM_THREADS, GEMM_SMEM>>>(x, c, hw1, hb1, hw2, hb2);
    adam_kernel<<<B_SAMP / 4, 128>>>(out);
}